// round 6
// baseline (speedup 1.0000x reference)
#include <cuda_runtime.h>
#include <math.h>

#define LSEQ   2048
#define NB     2
#define EMB    256
#define NH     8
#define HD     32
#define MROWS  (LSEQ*NB)           // 4096
#define ATT_SCALE 0.17677669529663687f   // 1/sqrt(32)

// ---- scratch (static device globals; no runtime allocation) ----
__device__ float g_Q[(size_t)NB*NH*LSEQ*HD];   // [bh][l][d]
__device__ float g_K[(size_t)NB*NH*LSEQ*HD];
__device__ float g_V[(size_t)NB*NH*LSEQ*HD];
__device__ float g_O[(size_t)MROWS*EMB];       // [l*B+b][e]

// ============================================================
// Fused QKV projection: Y = X @ W + b, scattered into [bh][l][d]
// grid (MROWS/64, EMB/64, 3), block 256
// ============================================================
__global__ __launch_bounds__(256) void qkv_proj(
    const float* __restrict__ xq, const float* __restrict__ xk, const float* __restrict__ xv,
    const float* __restrict__ Wq, const float* __restrict__ bq,
    const float* __restrict__ Wk, const float* __restrict__ bk,
    const float* __restrict__ Wv, const float* __restrict__ bv)
{
    __shared__ float As[64][17];
    __shared__ float Bs[16][68];

    const float *X, *W, *bias; float* out;
    if (blockIdx.z == 0)      { X = xq; W = Wq; bias = bq; out = g_Q; }
    else if (blockIdx.z == 1) { X = xk; W = Wk; bias = bk; out = g_K; }
    else                      { X = xv; W = Wv; bias = bv; out = g_V; }

    const int tid = threadIdx.x;
    const int tx = tid & 15, ty = tid >> 4;
    const int row0 = blockIdx.x * 64;
    const int col0 = blockIdx.y * 64;

    float acc[4][4];
    #pragma unroll
    for (int i = 0; i < 4; i++)
        #pragma unroll
        for (int j = 0; j < 4; j++) acc[i][j] = 0.f;

    const int ar = tid >> 2;            // 0..63
    const int ac = (tid & 3) << 2;      // 0,4,8,12
    const int br = tid >> 4;            // 0..15
    const int bc = (tid & 15) << 2;     // 0..60

    for (int k0 = 0; k0 < EMB; k0 += 16) {
        float4 a4 = *(const float4*)(X + (size_t)(row0 + ar) * EMB + k0 + ac);
        As[ar][ac+0] = a4.x; As[ar][ac+1] = a4.y; As[ar][ac+2] = a4.z; As[ar][ac+3] = a4.w;
        float4 b4 = *(const float4*)(W + (size_t)(k0 + br) * EMB + col0 + bc);
        Bs[br][bc+0] = b4.x; Bs[br][bc+1] = b4.y; Bs[br][bc+2] = b4.z; Bs[br][bc+3] = b4.w;
        __syncthreads();
        #pragma unroll
        for (int kk = 0; kk < 16; kk++) {
            float a[4], b[4];
            #pragma unroll
            for (int i = 0; i < 4; i++) a[i] = As[ty*4 + i][kk];
            #pragma unroll
            for (int j = 0; j < 4; j++) b[j] = Bs[kk][tx + 16*j];
            #pragma unroll
            for (int i = 0; i < 4; i++)
                #pragma unroll
                for (int j = 0; j < 4; j++)
                    acc[i][j] = fmaf(a[i], b[j], acc[i][j]);
        }
        __syncthreads();
    }

    #pragma unroll
    for (int i = 0; i < 4; i++) {
        int m  = row0 + ty*4 + i;
        int l  = m >> 1;        // m / NB
        int bb = m & 1;         // m % NB
        #pragma unroll
        for (int j = 0; j < 4; j++) {
            int n = col0 + tx + 16*j;
            float v = acc[i][j] + bias[n];
            int h = n >> 5, d = n & 31;
            out[(((size_t)bb * NH + h) * LSEQ + l) * HD + d] = v;
        }
    }
}

// ============================================================
// Flash attention: one CTA per (64-query tile, bh).
// grid (LSEQ/64, NB*NH), block 256
// ============================================================
__global__ __launch_bounds__(256) void attn_kernel()
{
    __shared__ float Qs[64][33];
    __shared__ float Ks[64][33];
    __shared__ float Vs[64][32];           // unpadded: float4 reads in PV phase
    __shared__ float Ss[64][65];
    __shared__ float row_m[64], row_l[64], row_c[64];

    const int bh = blockIdx.y;             // = b*NH + h
    const int q0 = blockIdx.x * 64;
    const float* Qp = g_Q + (size_t)bh * LSEQ * HD;
    const float* Kp = g_K + (size_t)bh * LSEQ * HD;
    const float* Vp = g_V + (size_t)bh * LSEQ * HD;

    const int tid  = threadIdx.x;
    const int lane = tid & 31, warp = tid >> 5;
    const int tx = tid & 15, ty = tid >> 4;
    const int lr = tid >> 2;               // load row 0..63
    const int lc = (tid & 3) << 3;         // load col 0,8,16,24

    // load Q tile
    {
        float4 v0 = *(const float4*)(Qp + (size_t)(q0 + lr) * HD + lc);
        float4 v1 = *(const float4*)(Qp + (size_t)(q0 + lr) * HD + lc + 4);
        Qs[lr][lc+0] = v0.x; Qs[lr][lc+1] = v0.y; Qs[lr][lc+2] = v0.z; Qs[lr][lc+3] = v0.w;
        Qs[lr][lc+4] = v1.x; Qs[lr][lc+5] = v1.y; Qs[lr][lc+6] = v1.z; Qs[lr][lc+7] = v1.w;
    }
    if (tid < 64) { row_m[tid] = -1e30f; row_l[tid] = 0.f; }

    const int ro = tid >> 2;               // output row 0..63
    const int cg = tid & 3;                // output col group: cols cg*8 .. cg*8+7
    float oacc[8];
    #pragma unroll
    for (int i = 0; i < 8; i++) oacc[i] = 0.f;

    for (int kt = 0; kt < LSEQ; kt += 64) {
        // load K,V tiles
        {
            float4 v0 = *(const float4*)(Kp + (size_t)(kt + lr) * HD + lc);
            float4 v1 = *(const float4*)(Kp + (size_t)(kt + lr) * HD + lc + 4);
            Ks[lr][lc+0] = v0.x; Ks[lr][lc+1] = v0.y; Ks[lr][lc+2] = v0.z; Ks[lr][lc+3] = v0.w;
            Ks[lr][lc+4] = v1.x; Ks[lr][lc+5] = v1.y; Ks[lr][lc+6] = v1.z; Ks[lr][lc+7] = v1.w;
            float4 w0 = *(const float4*)(Vp + (size_t)(kt + lr) * HD + lc);
            float4 w1 = *(const float4*)(Vp + (size_t)(kt + lr) * HD + lc + 4);
            *(float4*)&Vs[lr][lc]     = w0;
            *(float4*)&Vs[lr][lc + 4] = w1;
        }
        __syncthreads();

        // S = (Q Kt) * scale  -> Ss
        {
            float s[4][4];
            #pragma unroll
            for (int i = 0; i < 4; i++)
                #pragma unroll
                for (int j = 0; j < 4; j++) s[i][j] = 0.f;
            #pragma unroll
            for (int kk = 0; kk < HD; kk++) {
                float a[4], b[4];
                #pragma unroll
                for (int i = 0; i < 4; i++) a[i] = Qs[ty*4 + i][kk];
                #pragma unroll
                for (int j = 0; j < 4; j++) b[j] = Ks[tx + 16*j][kk];
                #pragma unroll
                for (int i = 0; i < 4; i++)
                    #pragma unroll
                    for (int j = 0; j < 4; j++)
                        s[i][j] = fmaf(a[i], b[j], s[i][j]);
            }
            #pragma unroll
            for (int i = 0; i < 4; i++)
                #pragma unroll
                for (int j = 0; j < 4; j++)
                    Ss[ty*4 + i][tx + 16*j] = s[i][j] * ATT_SCALE;
        }
        __syncthreads();

        // online softmax: warp w owns rows w*8 .. w*8+7
        #pragma unroll
        for (int rr = 0; rr < 8; rr++) {
            int r = warp * 8 + rr;
            float v0 = Ss[r][lane];
            float v1 = Ss[r][lane + 32];
            float mx = fmaxf(v0, v1);
            #pragma unroll
            for (int off = 16; off > 0; off >>= 1)
                mx = fmaxf(mx, __shfl_xor_sync(0xffffffffu, mx, off));
            float mo = row_m[r];
            float mn = fmaxf(mo, mx);
            float p0 = __expf(v0 - mn);
            float p1 = __expf(v1 - mn);
            Ss[r][lane]      = p0;
            Ss[r][lane + 32] = p1;
            float sum = p0 + p1;
            #pragma unroll
            for (int off = 16; off > 0; off >>= 1)
                sum += __shfl_xor_sync(0xffffffffu, sum, off);
            if (lane == 0) {
                float cor = __expf(mo - mn);    // 0 on first tile
                row_c[r] = cor;
                row_l[r] = row_l[r] * cor + sum;
                row_m[r] = mn;
            }
        }
        __syncthreads();

        // O += P @ V (with rescale)
        {
            float cor = row_c[ro];
            #pragma unroll
            for (int i = 0; i < 8; i++) oacc[i] *= cor;
            #pragma unroll 8
            for (int j = 0; j < 64; j++) {
                float p = Ss[ro][j];
                float4 va = *(const float4*)&Vs[j][cg*8];
                float4 vb = *(const float4*)&Vs[j][cg*8 + 4];
                oacc[0] = fmaf(p, va.x, oacc[0]);
                oacc[1] = fmaf(p, va.y, oacc[1]);
                oacc[2] = fmaf(p, va.z, oacc[2]);
                oacc[3] = fmaf(p, va.w, oacc[3]);
                oacc[4] = fmaf(p, vb.x, oacc[4]);
                oacc[5] = fmaf(p, vb.y, oacc[5]);
                oacc[6] = fmaf(p, vb.z, oacc[6]);
                oacc[7] = fmaf(p, vb.w, oacc[7]);
            }
        }
        __syncthreads();
    }

    // normalize + write O in [l][b][e] layout
    const float inv = 1.f / row_l[ro];
    const int b = bh / NH, h = bh % NH;
    const size_t obase = ((size_t)(q0 + ro) * NB + b) * EMB + h * HD + cg * 8;
    #pragma unroll
    for (int i = 0; i < 8; i++)
        g_O[obase + i] = oacc[i] * inv;
}

// ============================================================
// Output projection: out = O @ Wp + bp  (row-major [m][n])
// grid (MROWS/64, EMB/64), block 256
// ============================================================
__global__ __launch_bounds__(256) void out_proj(
    const float* __restrict__ Wp, const float* __restrict__ bp,
    float* __restrict__ out)
{
    __shared__ float As[64][17];
    __shared__ float Bs[16][68];

    const int tid = threadIdx.x;
    const int tx = tid & 15, ty = tid >> 4;
    const int row0 = blockIdx.x * 64;
    const int col0 = blockIdx.y * 64;

    float acc[4][4];
    #pragma unroll
    for (int i = 0; i < 4; i++)
        #pragma unroll
        for (int j = 0; j < 4; j++) acc[i][j] = 0.f;

    const int ar = tid >> 2;
    const int ac = (tid & 3) << 2;
    const int br = tid >> 4;
    const int bc = (tid & 15) << 2;

    for (int k0 = 0; k0 < EMB; k0 += 16) {
        float4 a4 = *(const float4*)(g_O + (size_t)(row0 + ar) * EMB + k0 + ac);
        As[ar][ac+0] = a4.x; As[ar][ac+1] = a4.y; As[ar][ac+2] = a4.z; As[ar][ac+3] = a4.w;
        float4 b4 = *(const float4*)(Wp + (size_t)(k0 + br) * EMB + col0 + bc);
        Bs[br][bc+0] = b4.x; Bs[br][bc+1] = b4.y; Bs[br][bc+2] = b4.z; Bs[br][bc+3] = b4.w;
        __syncthreads();
        #pragma unroll
        for (int kk = 0; kk < 16; kk++) {
            float a[4], b[4];
            #pragma unroll
            for (int i = 0; i < 4; i++) a[i] = As[ty*4 + i][kk];
            #pragma unroll
            for (int j = 0; j < 4; j++) b[j] = Bs[kk][tx + 16*j];
            #pragma unroll
            for (int i = 0; i < 4; i++)
                #pragma unroll
                for (int j = 0; j < 4; j++)
                    acc[i][j] = fmaf(a[i], b[j], acc[i][j]);
        }
        __syncthreads();
    }

    #pragma unroll
    for (int i = 0; i < 4; i++) {
        int m = row0 + ty*4 + i;
        #pragma unroll
        for (int j = 0; j < 4; j++) {
            int n = col0 + tx + 16*j;
            out[(size_t)m * EMB + n] = acc[i][j] + bp[n];
        }
    }
}

// ============================================================
extern "C" void kernel_launch(void* const* d_in, const int* in_sizes, int n_in,
                              void* d_out, int out_size)
{
    const float* query = (const float*)d_in[0];
    const float* key_  = (const float*)d_in[1];
    const float* value = (const float*)d_in[2];
    const float* Wq    = (const float*)d_in[3];
    const float* bq    = (const float*)d_in[4];
    const float* Wk    = (const float*)d_in[5];
    const float* bk    = (const float*)d_in[6];
    const float* Wv    = (const float*)d_in[7];
    const float* bv    = (const float*)d_in[8];
    const float* Wp    = (const float*)d_in[9];
    const float* bp    = (const float*)d_in[10];
    float* out = (float*)d_out;

    dim3 g1(MROWS/64, EMB/64, 3);
    qkv_proj<<<g1, 256>>>(query, key_, value, Wq, bq, Wk, bk, Wv, bv);

    dim3 g2(LSEQ/64, NB*NH);
    attn_kernel<<<g2, 256>>>();

    dim3 g3(MROWS/64, EMB/64);
    out_proj<<<g3, 256>>>(Wp, bp, out);
}

// round 10
// speedup vs baseline: 4.6377x; 4.6377x over previous
#include <cuda_runtime.h>
#include <cuda_fp16.h>
#include <cstdint>
#include <stdint.h>
#include <math.h>

#define LSEQ   2048
#define NB     2
#define EMB    256
#define NH     8
#define HD     32
#define MROWS  (LSEQ*NB)                 // 4096
// (1/sqrt(32)) * log2(e): softmax done in base-2 domain
#define SCL2E  0.2550052554286127f

// ---- scratch (static device globals; no runtime allocation) ----
__device__ __half g_Q[(size_t)NB*NH*LSEQ*HD];   // [bh][l][d] fp16
__device__ __half g_K[(size_t)NB*NH*LSEQ*HD];
__device__ __half g_V[(size_t)NB*NH*LSEQ*HD];
__device__ float  g_O[(size_t)MROWS*EMB];       // [l*B+b][e] fp32

// ---------------- PTX helpers ----------------
__device__ __forceinline__ uint32_t smem_u32(const void* p) {
    uint32_t a;
    asm("{ .reg .u64 t; cvta.to.shared.u64 t, %1; cvt.u32.u64 %0, t; }"
        : "=r"(a) : "l"(p));
    return a;
}
__device__ __forceinline__ void ldsm_x4(uint32_t& r0, uint32_t& r1, uint32_t& r2, uint32_t& r3,
                                        uint32_t addr) {
    asm volatile("ldmatrix.sync.aligned.m8n8.x4.shared.b16 {%0,%1,%2,%3}, [%4];"
                 : "=r"(r0), "=r"(r1), "=r"(r2), "=r"(r3) : "r"(addr));
}
__device__ __forceinline__ void ldsm_x4_t(uint32_t& r0, uint32_t& r1, uint32_t& r2, uint32_t& r3,
                                          uint32_t addr) {
    asm volatile("ldmatrix.sync.aligned.m8n8.x4.trans.shared.b16 {%0,%1,%2,%3}, [%4];"
                 : "=r"(r0), "=r"(r1), "=r"(r2), "=r"(r3) : "r"(addr));
}
__device__ __forceinline__ void mma16816(float* c,
                                         uint32_t a0, uint32_t a1, uint32_t a2, uint32_t a3,
                                         uint32_t b0, uint32_t b1) {
    asm volatile("mma.sync.aligned.m16n8k16.row.col.f32.f16.f16.f32 "
                 "{%0,%1,%2,%3}, {%4,%5,%6,%7}, {%8,%9}, {%0,%1,%2,%3};"
                 : "+f"(c[0]), "+f"(c[1]), "+f"(c[2]), "+f"(c[3])
                 : "r"(a0), "r"(a1), "r"(a2), "r"(a3), "r"(b0), "r"(b1));
}
__device__ __forceinline__ float ex2f(float x) {
    float y; asm("ex2.approx.f32 %0, %1;" : "=f"(y) : "f"(x)); return y;
}
__device__ __forceinline__ uint32_t packh2(float a, float b) {
    __half2 h = __floats2half2_rn(a, b);
    return *(uint32_t*)&h;
}

// ============================================================
// Fused QKV projection: Y = X @ W + b, scattered into [bh][l][d] as fp16
// grid (MROWS/64, EMB/64, 3), block 256
// ============================================================
__global__ __launch_bounds__(256) void qkv_proj(
    const float* __restrict__ xq, const float* __restrict__ xk, const float* __restrict__ xv,
    const float* __restrict__ Wq, const float* __restrict__ bq,
    const float* __restrict__ Wk, const float* __restrict__ bk,
    const float* __restrict__ Wv, const float* __restrict__ bv)
{
    __shared__ float As[64][17];
    __shared__ float Bs[16][68];

    const float *X, *W, *bias; __half* out;
    if (blockIdx.z == 0)      { X = xq; W = Wq; bias = bq; out = g_Q; }
    else if (blockIdx.z == 1) { X = xk; W = Wk; bias = bk; out = g_K; }
    else                      { X = xv; W = Wv; bias = bv; out = g_V; }

    const int tid = threadIdx.x;
    const int tx = tid & 15, ty = tid >> 4;
    const int row0 = blockIdx.x * 64;
    const int col0 = blockIdx.y * 64;

    float acc[4][4];
    #pragma unroll
    for (int i = 0; i < 4; i++)
        #pragma unroll
        for (int j = 0; j < 4; j++) acc[i][j] = 0.f;

    const int ar = tid >> 2;
    const int ac = (tid & 3) << 2;
    const int br = tid >> 4;
    const int bc = (tid & 15) << 2;

    for (int k0 = 0; k0 < EMB; k0 += 16) {
        float4 a4 = *(const float4*)(X + (size_t)(row0 + ar) * EMB + k0 + ac);
        As[ar][ac+0] = a4.x; As[ar][ac+1] = a4.y; As[ar][ac+2] = a4.z; As[ar][ac+3] = a4.w;
        float4 b4 = *(const float4*)(W + (size_t)(k0 + br) * EMB + col0 + bc);
        Bs[br][bc+0] = b4.x; Bs[br][bc+1] = b4.y; Bs[br][bc+2] = b4.z; Bs[br][bc+3] = b4.w;
        __syncthreads();
        #pragma unroll
        for (int kk = 0; kk < 16; kk++) {
            float a[4], b[4];
            #pragma unroll
            for (int i = 0; i < 4; i++) a[i] = As[ty*4 + i][kk];
            #pragma unroll
            for (int j = 0; j < 4; j++) b[j] = Bs[kk][tx + 16*j];
            #pragma unroll
            for (int i = 0; i < 4; i++)
                #pragma unroll
                for (int j = 0; j < 4; j++)
                    acc[i][j] = fmaf(a[i], b[j], acc[i][j]);
        }
        __syncthreads();
    }

    #pragma unroll
    for (int i = 0; i < 4; i++) {
        int m  = row0 + ty*4 + i;
        int l  = m >> 1;
        int bb = m & 1;
        #pragma unroll
        for (int j = 0; j < 4; j++) {
            int n = col0 + tx + 16*j;
            float v = acc[i][j] + bias[n];
            int h = n >> 5, d = n & 31;
            out[(((size_t)bb * NH + h) * LSEQ + l) * HD + d] = __float2half_rn(v);
        }
    }
}

// ============================================================
// FlashAttention-2 with fp16 mma.sync (fp32 accum).
// grid (LSEQ/64, NB*NH), block 128 (4 warps; each warp owns 16 Q rows)
// ============================================================
__global__ __launch_bounds__(128) void attn_kernel()
{
    __shared__ __half Qs[64][40];   // 40-pad: 80B rows -> conflict-free ldmatrix
    __shared__ __half Ks[64][40];
    __shared__ __half Vs[64][40];

    const int bh = blockIdx.y;
    const int q0 = blockIdx.x * 64;
    const __half* Qp = g_Q + (size_t)bh * LSEQ * HD;
    const __half* Kp = g_K + (size_t)bh * LSEQ * HD;
    const __half* Vp = g_V + (size_t)bh * LSEQ * HD;

    const int tid  = threadIdx.x;
    const int lane = tid & 31, warp = tid >> 5;

    // ---- load Q tile (each thread: one half-row = 16 halfs = 2x uint4) ----
    {
        int row = tid >> 1, ch = (tid & 1) * 16;
        const uint4* src = (const uint4*)(Qp + (size_t)(q0 + row) * HD + ch);
        uint4 v0 = src[0], v1 = src[1];
        *(uint4*)&Qs[row][ch]     = v0;
        *(uint4*)&Qs[row][ch + 8] = v1;
    }
    __syncthreads();

    // ---- hoist Q fragments (2 k-steps of 16) ----
    uint32_t qa[2][4];
    {
        int r = 16*warp + (lane & 7) + ((lane >> 3) & 1) * 8;
        int cbase = ((lane >> 4) & 1) * 8;
        ldsm_x4(qa[0][0], qa[0][1], qa[0][2], qa[0][3], smem_u32(&Qs[r][cbase]));
        ldsm_x4(qa[1][0], qa[1][1], qa[1][2], qa[1][3], smem_u32(&Qs[r][16 + cbase]));
    }

    float oc[4][4];
    #pragma unroll
    for (int d = 0; d < 4; d++)
        #pragma unroll
        for (int i = 0; i < 4; i++) oc[d][i] = 0.f;
    float m0 = -1e30f, m1 = -1e30f, l0 = 0.f, l1 = 0.f;

    // precomputed ldmatrix lane addressing
    const int krow = (lane & 7);                  // within 8-row group
    const int kcol = ((lane >> 3) & 3) * 8;       // K: k-step column selector (0,8,16,24)
    const int vrow = (lane & 7) + ((lane >> 3) & 1) * 8;
    const int vcol = ((lane >> 4) & 1) * 8;

    for (int kt = 0; kt < LSEQ; kt += 64) {
        __syncthreads();   // protect Ks/Vs from overwrite while prior ldmatrix in flight
        {
            int row = tid >> 1, ch = (tid & 1) * 16;
            const uint4* sk = (const uint4*)(Kp + (size_t)(kt + row) * HD + ch);
            uint4 k0v = sk[0], k1v = sk[1];
            *(uint4*)&Ks[row][ch]     = k0v;
            *(uint4*)&Ks[row][ch + 8] = k1v;
            const uint4* sv = (const uint4*)(Vp + (size_t)(kt + row) * HD + ch);
            uint4 v0v = sv[0], v1v = sv[1];
            *(uint4*)&Vs[row][ch]     = v0v;
            *(uint4*)&Vs[row][ch + 8] = v1v;
        }
        __syncthreads();

        // ---- S = Q K^T : 8 n-tiles of 8 cols ----
        float sc[8][4];
        #pragma unroll
        for (int j = 0; j < 8; j++) {
            sc[j][0] = sc[j][1] = sc[j][2] = sc[j][3] = 0.f;
            uint32_t kb0, kb1, kb2, kb3;
            ldsm_x4(kb0, kb1, kb2, kb3, smem_u32(&Ks[8*j + krow][kcol]));
            mma16816(sc[j], qa[0][0], qa[0][1], qa[0][2], qa[0][3], kb0, kb1);
            mma16816(sc[j], qa[1][0], qa[1][1], qa[1][2], qa[1][3], kb2, kb3);
        }

        // ---- online softmax (base-2), rows r=lane/4 (c0,c1) and r+8 (c2,c3) ----
        float mt0 = -1e30f, mt1 = -1e30f;
        #pragma unroll
        for (int j = 0; j < 8; j++) {
            sc[j][0] *= SCL2E; sc[j][1] *= SCL2E;
            sc[j][2] *= SCL2E; sc[j][3] *= SCL2E;
            mt0 = fmaxf(mt0, fmaxf(sc[j][0], sc[j][1]));
            mt1 = fmaxf(mt1, fmaxf(sc[j][2], sc[j][3]));
        }
        mt0 = fmaxf(mt0, __shfl_xor_sync(0xffffffffu, mt0, 1));
        mt0 = fmaxf(mt0, __shfl_xor_sync(0xffffffffu, mt0, 2));
        mt1 = fmaxf(mt1, __shfl_xor_sync(0xffffffffu, mt1, 1));
        mt1 = fmaxf(mt1, __shfl_xor_sync(0xffffffffu, mt1, 2));

        float mn0 = fmaxf(m0, mt0), mn1 = fmaxf(m1, mt1);
        float cor0 = ex2f(m0 - mn0), cor1 = ex2f(m1 - mn1);
        m0 = mn0; m1 = mn1;

        uint32_t pf[8][2];
        float rs0 = 0.f, rs1 = 0.f;
        #pragma unroll
        for (int j = 0; j < 8; j++) {
            float p0 = ex2f(sc[j][0] - mn0);
            float p1 = ex2f(sc[j][1] - mn0);
            float p2 = ex2f(sc[j][2] - mn1);
            float p3 = ex2f(sc[j][3] - mn1);
            rs0 += p0 + p1; rs1 += p2 + p3;
            pf[j][0] = packh2(p0, p1);
            pf[j][1] = packh2(p2, p3);
        }
        rs0 += __shfl_xor_sync(0xffffffffu, rs0, 1);
        rs0 += __shfl_xor_sync(0xffffffffu, rs0, 2);
        rs1 += __shfl_xor_sync(0xffffffffu, rs1, 1);
        rs1 += __shfl_xor_sync(0xffffffffu, rs1, 2);
        l0 = l0 * cor0 + rs0;
        l1 = l1 * cor1 + rs1;

        #pragma unroll
        for (int d = 0; d < 4; d++) {
            oc[d][0] *= cor0; oc[d][1] *= cor0;
            oc[d][2] *= cor1; oc[d][3] *= cor1;
        }

        // ---- O += P V : 4 k-steps of 16 keys; d-tiles {0,8,16,24} ----
        #pragma unroll
        for (int kk = 0; kk < 4; kk++) {
            uint32_t vb0, vb1, vb2, vb3, wb0, wb1, wb2, wb3;
            ldsm_x4_t(vb0, vb1, vb2, vb3, smem_u32(&Vs[16*kk + vrow][vcol]));
            ldsm_x4_t(wb0, wb1, wb2, wb3, smem_u32(&Vs[16*kk + vrow][16 + vcol]));
            uint32_t a0 = pf[2*kk][0], a1 = pf[2*kk][1];
            uint32_t a2 = pf[2*kk+1][0], a3 = pf[2*kk+1][1];
            mma16816(oc[0], a0, a1, a2, a3, vb0, vb1);
            mma16816(oc[1], a0, a1, a2, a3, vb2, vb3);
            mma16816(oc[2], a0, a1, a2, a3, wb0, wb1);
            mma16816(oc[3], a0, a1, a2, a3, wb2, wb3);
        }
    }

    // ---- epilogue: normalize, write g_O [l][b][e] ----
    const float inv0 = 1.f / l0, inv1 = 1.f / l1;
    const int r = lane >> 2, c = (lane & 3) * 2;
    const int b = bh >> 3, h = bh & 7;
    const int qrow0 = q0 + 16*warp + r;
    const int qrow1 = qrow0 + 8;
    #pragma unroll
    for (int d = 0; d < 4; d++) {
        float2 v0 = make_float2(oc[d][0] * inv0, oc[d][1] * inv0);
        float2 v1 = make_float2(oc[d][2] * inv1, oc[d][3] * inv1);
        *(float2*)&g_O[((size_t)qrow0 * NB + b) * EMB + h * HD + 8*d + c] = v0;
        *(float2*)&g_O[((size_t)qrow1 * NB + b) * EMB + h * HD + 8*d + c] = v1;
    }
}

// ============================================================
// Output projection: out = O @ Wp + bp
// grid (MROWS/64, EMB/64), block 256
// ============================================================
__global__ __launch_bounds__(256) void out_proj(
    const float* __restrict__ Wp, const float* __restrict__ bp,
    float* __restrict__ out)
{
    __shared__ float As[64][17];
    __shared__ float Bs[16][68];

    const int tid = threadIdx.x;
    const int tx = tid & 15, ty = tid >> 4;
    const int row0 = blockIdx.x * 64;
    const int col0 = blockIdx.y * 64;

    float acc[4][4];
    #pragma unroll
    for (int i = 0; i < 4; i++)
        #pragma unroll
        for (int j = 0; j < 4; j++) acc[i][j] = 0.f;

    const int ar = tid >> 2;
    const int ac = (tid & 3) << 2;
    const int br = tid >> 4;
    const int bc = (tid & 15) << 2;

    for (int k0 = 0; k0 < EMB; k0 += 16) {
        float4 a4 = *(const float4*)(g_O + (size_t)(row0 + ar) * EMB + k0 + ac);
        As[ar][ac+0] = a4.x; As[ar][ac+1] = a4.y; As[ar][ac+2] = a4.z; As[ar][ac+3] = a4.w;
        float4 b4 = *(const float4*)(Wp + (size_t)(k0 + br) * EMB + col0 + bc);
        Bs[br][bc+0] = b4.x; Bs[br][bc+1] = b4.y; Bs[br][bc+2] = b4.z; Bs[br][bc+3] = b4.w;
        __syncthreads();
        #pragma unroll
        for (int kk = 0; kk < 16; kk++) {
            float a[4], b[4];
            #pragma unroll
            for (int i = 0; i < 4; i++) a[i] = As[ty*4 + i][kk];
            #pragma unroll
            for (int j = 0; j < 4; j++) b[j] = Bs[kk][tx + 16*j];
            #pragma unroll
            for (int i = 0; i < 4; i++)
                #pragma unroll
                for (int j = 0; j < 4; j++)
                    acc[i][j] = fmaf(a[i], b[j], acc[i][j]);
        }
        __syncthreads();
    }

    #pragma unroll
    for (int i = 0; i < 4; i++) {
        int m = row0 + ty*4 + i;
        #pragma unroll
        for (int j = 0; j < 4; j++) {
            int n = col0 + tx + 16*j;
            out[(size_t)m * EMB + n] = acc[i][j] + bp[n];
        }
    }
}

// ============================================================
extern "C" void kernel_launch(void* const* d_in, const int* in_sizes, int n_in,
                              void* d_out, int out_size)
{
    const float* query = (const float*)d_in[0];
    const float* key_  = (const float*)d_in[1];
    const float* value = (const float*)d_in[2];
    const float* Wq    = (const float*)d_in[3];
    const float* bq    = (const float*)d_in[4];
    const float* Wk    = (const float*)d_in[5];
    const float* bk    = (const float*)d_in[6];
    const float* Wv    = (const float*)d_in[7];
    const float* bv    = (const float*)d_in[8];
    const float* Wp    = (const float*)d_in[9];
    const float* bp    = (const float*)d_in[10];
    float* out = (float*)d_out;

    dim3 g1(MROWS/64, EMB/64, 3);
    qkv_proj<<<g1, 256>>>(query, key_, value, Wq, bq, Wk, bk, Wv, bv);

    dim3 g2(LSEQ/64, NB*NH);
    attn_kernel<<<g2, 128>>>();

    dim3 g3(MROWS/64, EMB/64);
    out_proj<<<g3, 256>>>(Wp, bp, out);
}

// round 11
// speedup vs baseline: 5.6279x; 1.2135x over previous
#include <cuda_runtime.h>
#include <cuda_fp16.h>
#include <cstdint>
#include <stdint.h>
#include <math.h>

#define LSEQ   2048
#define NB     2
#define EMB    256
#define NH     8
#define HD     32
#define MROWS  (LSEQ*NB)                 // 4096
// (1/sqrt(32)) * log2(e): folded into Q at projection time
#define SCL2E  0.2550052554286127f

// ---- scratch (static device globals; no runtime allocation) ----
__device__ __half g_Q[(size_t)NB*NH*LSEQ*HD];   // [bh][l][d] fp16 (pre-scaled by SCL2E)
__device__ __half g_K[(size_t)NB*NH*LSEQ*HD];
__device__ __half g_V[(size_t)NB*NH*LSEQ*HD];
__device__ float  g_O[(size_t)MROWS*EMB];       // [l*B+b][e] fp32

// ---------------- PTX helpers ----------------
__device__ __forceinline__ uint32_t smem_u32(const void* p) {
    uint32_t a;
    asm("{ .reg .u64 t; cvta.to.shared.u64 t, %1; cvt.u32.u64 %0, t; }"
        : "=r"(a) : "l"(p));
    return a;
}
__device__ __forceinline__ void ldsm_x4(uint32_t& r0, uint32_t& r1, uint32_t& r2, uint32_t& r3,
                                        uint32_t addr) {
    asm volatile("ldmatrix.sync.aligned.m8n8.x4.shared.b16 {%0,%1,%2,%3}, [%4];"
                 : "=r"(r0), "=r"(r1), "=r"(r2), "=r"(r3) : "r"(addr));
}
__device__ __forceinline__ void ldsm_x4_t(uint32_t& r0, uint32_t& r1, uint32_t& r2, uint32_t& r3,
                                          uint32_t addr) {
    asm volatile("ldmatrix.sync.aligned.m8n8.x4.trans.shared.b16 {%0,%1,%2,%3}, [%4];"
                 : "=r"(r0), "=r"(r1), "=r"(r2), "=r"(r3) : "r"(addr));
}
__device__ __forceinline__ void mma16816(float* c,
                                         uint32_t a0, uint32_t a1, uint32_t a2, uint32_t a3,
                                         uint32_t b0, uint32_t b1) {
    asm volatile("mma.sync.aligned.m16n8k16.row.col.f32.f16.f16.f32 "
                 "{%0,%1,%2,%3}, {%4,%5,%6,%7}, {%8,%9}, {%0,%1,%2,%3};"
                 : "+f"(c[0]), "+f"(c[1]), "+f"(c[2]), "+f"(c[3])
                 : "r"(a0), "r"(a1), "r"(a2), "r"(a3), "r"(b0), "r"(b1));
}
__device__ __forceinline__ float ex2f(float x) {
    float y; asm("ex2.approx.f32 %0, %1;" : "=f"(y) : "f"(x)); return y;
}
__device__ __forceinline__ uint32_t hex2(uint32_t x) {   // packed f16x2 2^x
    uint32_t y; asm("ex2.approx.f16x2 %0, %1;" : "=r"(y) : "r"(x)); return y;
}
__device__ __forceinline__ uint32_t packh2(float a, float b) {
    __half2 h = __floats2half2_rn(a, b);
    return *(uint32_t*)&h;
}

// ============================================================
// fp16-split tensor-core GEMM (near-fp32 accuracy):
//   C = A(fp32)[M=4096,K=256] x B(fp32)[K=256,N=256] + bias
//   hi/lo split, C ~= hi*hi + hi*lo + lo*hi  (3 HMMA, fp32 accum)
// mode 0/1/2: A=x{q,k,v}, B=W{q,k,v}, epilogue -> fp16 scatter into g_{Q,K,V}
//             (mode 0 additionally scales by SCL2E)
// mode 3:     A=g_O, B=Wp, epilogue -> fp32 d_out (+bp)
// grid (64, 4, nz), block 128 (4 warps; warp w = rows 16w..16w+15, all 64 cols)
// ============================================================
__global__ __launch_bounds__(128) void split_gemm(
    int mode_base,
    const float* __restrict__ xq, const float* __restrict__ xk, const float* __restrict__ xv,
    const float* __restrict__ Wq, const float* __restrict__ bq,
    const float* __restrict__ Wk, const float* __restrict__ bk,
    const float* __restrict__ Wv, const float* __restrict__ bv,
    const float* __restrict__ Wp, const float* __restrict__ bp,
    float* __restrict__ outp)
{
    __shared__ __half Ash[64][72];   // 72-pad: 144B rows, conflict-free ldmatrix
    __shared__ __half Asl[64][72];
    __shared__ __half Bsh[64][72];
    __shared__ __half Bsl[64][72];

    const int mode = mode_base + blockIdx.z;
    const float *A, *B, *bias;
    if (mode == 0)      { A = xq;  B = Wq; bias = bq; }
    else if (mode == 1) { A = xk;  B = Wk; bias = bk; }
    else if (mode == 2) { A = xv;  B = Wv; bias = bv; }
    else                { A = g_O; B = Wp; bias = bp; }

    const int tid = threadIdx.x;
    const int lane = tid & 31, warp = tid >> 5;
    const int row0 = blockIdx.x * 64;
    const int col0 = blockIdx.y * 64;

    float acc[8][4];
    #pragma unroll
    for (int i = 0; i < 8; i++)
        #pragma unroll
        for (int j = 0; j < 4; j++) acc[i][j] = 0.f;

    const int lrow = tid >> 1;          // 0..63
    const int lc0  = (tid & 1) * 32;    // 0 or 32

    for (int kc = 0; kc < 4; kc++) {
        const int k0 = kc * 64;
        __syncthreads();   // protect smem reuse across chunks
        // ---- load + split-convert A chunk (rows row0+., k k0..k0+63) and B chunk ----
        #pragma unroll
        for (int v = 0; v < 8; v++) {
            const int c = lc0 + v * 4;
            float4 a4 = *(const float4*)(A + (size_t)(row0 + lrow) * EMB + k0 + c);
            __half h0 = __float2half_rn(a4.x), h1 = __float2half_rn(a4.y);
            __half h2 = __float2half_rn(a4.z), h3 = __float2half_rn(a4.w);
            *(__half2*)&Ash[lrow][c]   = __halves2half2(h0, h1);
            *(__half2*)&Ash[lrow][c+2] = __halves2half2(h2, h3);
            *(__half2*)&Asl[lrow][c]   = __floats2half2_rn(a4.x - __half2float(h0),
                                                           a4.y - __half2float(h1));
            *(__half2*)&Asl[lrow][c+2] = __floats2half2_rn(a4.z - __half2float(h2),
                                                           a4.w - __half2float(h3));
            float4 b4 = *(const float4*)(B + (size_t)(k0 + lrow) * EMB + col0 + c);
            __half g0 = __float2half_rn(b4.x), g1 = __float2half_rn(b4.y);
            __half g2 = __float2half_rn(b4.z), g3 = __float2half_rn(b4.w);
            *(__half2*)&Bsh[lrow][c]   = __halves2half2(g0, g1);
            *(__half2*)&Bsh[lrow][c+2] = __halves2half2(g2, g3);
            *(__half2*)&Bsl[lrow][c]   = __floats2half2_rn(b4.x - __half2float(g0),
                                                           b4.y - __half2float(g1));
            *(__half2*)&Bsl[lrow][c+2] = __floats2half2_rn(b4.z - __half2float(g2),
                                                           b4.w - __half2float(g3));
        }
        __syncthreads();

        // ---- 4 k16 steps ----
        #pragma unroll
        for (int s = 0; s < 4; s++) {
            const int arow = 16*warp + (lane & 7) + ((lane >> 3) & 1) * 8;
            const int akb  = 16*s + ((lane >> 4) & 1) * 8;
            uint32_t ah[4], al[4];
            ldsm_x4(ah[0], ah[1], ah[2], ah[3], smem_u32(&Ash[arow][akb]));
            ldsm_x4(al[0], al[1], al[2], al[3], smem_u32(&Asl[arow][akb]));
            const int brow = 16*s + (lane & 7) + ((lane >> 3) & 1) * 8;
            #pragma unroll
            for (int nt = 0; nt < 4; nt++) {
                const int nb = 16*nt + ((lane >> 4) & 1) * 8;
                uint32_t bh[4], bl[4];
                ldsm_x4_t(bh[0], bh[1], bh[2], bh[3], smem_u32(&Bsh[brow][nb]));
                ldsm_x4_t(bl[0], bl[1], bl[2], bl[3], smem_u32(&Bsl[brow][nb]));
                mma16816(acc[2*nt],   ah[0], ah[1], ah[2], ah[3], bh[0], bh[1]);
                mma16816(acc[2*nt],   ah[0], ah[1], ah[2], ah[3], bl[0], bl[1]);
                mma16816(acc[2*nt],   al[0], al[1], al[2], al[3], bh[0], bh[1]);
                mma16816(acc[2*nt+1], ah[0], ah[1], ah[2], ah[3], bh[2], bh[3]);
                mma16816(acc[2*nt+1], ah[0], ah[1], ah[2], ah[3], bl[2], bl[3]);
                mma16816(acc[2*nt+1], al[0], al[1], al[2], al[3], bh[2], bh[3]);
            }
        }
    }

    // ---- epilogue ----
    const int r = lane >> 2, cp = (lane & 3) * 2;
    if (mode < 3) {
        __half* outh = (mode == 0) ? g_Q : (mode == 1) ? g_K : g_V;
        const float scl = (mode == 0) ? SCL2E : 1.f;
        #pragma unroll
        for (int nt = 0; nt < 8; nt++) {
            const int n = col0 + 8*nt + cp;
            const float bb0 = bias[n], bb1 = bias[n+1];
            const int h = n >> 5, d = n & 31;
            #pragma unroll
            for (int hf = 0; hf < 2; hf++) {
                const int m = row0 + 16*warp + r + 8*hf;
                const int l = m >> 1, bb = m & 1;
                float v0 = (acc[nt][2*hf+0] + bb0) * scl;
                float v1 = (acc[nt][2*hf+1] + bb1) * scl;
                *(__half2*)&outh[(((size_t)bb * NH + h) * LSEQ + l) * HD + d] =
                    __floats2half2_rn(v0, v1);
            }
        }
    } else {
        #pragma unroll
        for (int nt = 0; nt < 8; nt++) {
            const int n = col0 + 8*nt + cp;
            const float bb0 = bias[n], bb1 = bias[n+1];
            #pragma unroll
            for (int hf = 0; hf < 2; hf++) {
                const int m = row0 + 16*warp + r + 8*hf;
                *(float2*)&outp[(size_t)m * EMB + n] =
                    make_float2(acc[nt][2*hf+0] + bb0, acc[nt][2*hf+1] + bb1);
            }
        }
    }
}

// ============================================================
// FlashAttention-2, fp16 mma.sync (fp32 accum), Q pre-scaled.
// grid (LSEQ/64, NB*NH), block 128 (4 warps; each warp owns 16 Q rows)
// ============================================================
__global__ __launch_bounds__(128) void attn_kernel()
{
    __shared__ __half Qs[64][40];   // 40-pad: 80B rows -> conflict-free ldmatrix
    __shared__ __half Ks[64][40];
    __shared__ __half Vs[64][40];

    const int bh = blockIdx.y;
    const int q0 = blockIdx.x * 64;
    const __half* Qp = g_Q + (size_t)bh * LSEQ * HD;
    const __half* Kp = g_K + (size_t)bh * LSEQ * HD;
    const __half* Vp = g_V + (size_t)bh * LSEQ * HD;

    const int tid  = threadIdx.x;
    const int lane = tid & 31, warp = tid >> 5;

    // ---- load Q tile ----
    {
        int row = tid >> 1, ch = (tid & 1) * 16;
        const uint4* src = (const uint4*)(Qp + (size_t)(q0 + row) * HD + ch);
        uint4 v0 = src[0], v1 = src[1];
        *(uint4*)&Qs[row][ch]     = v0;
        *(uint4*)&Qs[row][ch + 8] = v1;
    }
    __syncthreads();

    // ---- hoist Q fragments (2 k-steps of 16) ----
    uint32_t qa[2][4];
    {
        int r = 16*warp + (lane & 7) + ((lane >> 3) & 1) * 8;
        int cbase = ((lane >> 4) & 1) * 8;
        ldsm_x4(qa[0][0], qa[0][1], qa[0][2], qa[0][3], smem_u32(&Qs[r][cbase]));
        ldsm_x4(qa[1][0], qa[1][1], qa[1][2], qa[1][3], smem_u32(&Qs[r][16 + cbase]));
    }

    float oc[4][4];
    #pragma unroll
    for (int d = 0; d < 4; d++)
        #pragma unroll
        for (int i = 0; i < 4; i++) oc[d][i] = 0.f;
    float lacc[4] = {0.f, 0.f, 0.f, 0.f};          // row-sum via ones-MMA
    float m0 = -1e30f, m1 = -1e30f;

    const uint32_t ONES = 0x3C003C00u;             // half2(1,1)

    const int krow = (lane & 7);
    const int kcol = ((lane >> 3) & 3) * 8;
    const int vrow = (lane & 7) + ((lane >> 3) & 1) * 8;
    const int vcol = ((lane >> 4) & 1) * 8;

    for (int kt = 0; kt < LSEQ; kt += 64) {
        __syncthreads();
        {
            int row = tid >> 1, ch = (tid & 1) * 16;
            const uint4* sk = (const uint4*)(Kp + (size_t)(kt + row) * HD + ch);
            uint4 k0v = sk[0], k1v = sk[1];
            *(uint4*)&Ks[row][ch]     = k0v;
            *(uint4*)&Ks[row][ch + 8] = k1v;
            const uint4* sv = (const uint4*)(Vp + (size_t)(kt + row) * HD + ch);
            uint4 v0v = sv[0], v1v = sv[1];
            *(uint4*)&Vs[row][ch]     = v0v;
            *(uint4*)&Vs[row][ch + 8] = v1v;
        }
        __syncthreads();

        // ---- S = Q K^T (already in log2 domain: Q pre-scaled by SCL2E) ----
        float sc[8][4];
        #pragma unroll
        for (int j = 0; j < 8; j++) {
            sc[j][0] = sc[j][1] = sc[j][2] = sc[j][3] = 0.f;
            uint32_t kb0, kb1, kb2, kb3;
            ldsm_x4(kb0, kb1, kb2, kb3, smem_u32(&Ks[8*j + krow][kcol]));
            mma16816(sc[j], qa[0][0], qa[0][1], qa[0][2], qa[0][3], kb0, kb1);
            mma16816(sc[j], qa[1][0], qa[1][1], qa[1][2], qa[1][3], kb2, kb3);
        }

        // ---- online softmax (base-2) ----
        float mt0 = -1e30f, mt1 = -1e30f;
        #pragma unroll
        for (int j = 0; j < 8; j++) {
            mt0 = fmaxf(mt0, fmaxf(sc[j][0], sc[j][1]));
            mt1 = fmaxf(mt1, fmaxf(sc[j][2], sc[j][3]));
        }
        mt0 = fmaxf(mt0, __shfl_xor_sync(0xffffffffu, mt0, 1));
        mt0 = fmaxf(mt0, __shfl_xor_sync(0xffffffffu, mt0, 2));
        mt1 = fmaxf(mt1, __shfl_xor_sync(0xffffffffu, mt1, 1));
        mt1 = fmaxf(mt1, __shfl_xor_sync(0xffffffffu, mt1, 2));

        const float mn0 = fmaxf(m0, mt0), mn1 = fmaxf(m1, mt1);
        const float cor0 = ex2f(m0 - mn0), cor1 = ex2f(m1 - mn1);
        m0 = mn0; m1 = mn1;

        // P = 2^(s - mn) straight to packed fp16 via ex2.approx.f16x2
        uint32_t pf[8][2];
        #pragma unroll
        for (int j = 0; j < 8; j++) {
            pf[j][0] = hex2(packh2(sc[j][0] - mn0, sc[j][1] - mn0));
            pf[j][1] = hex2(packh2(sc[j][2] - mn1, sc[j][3] - mn1));
        }

        lacc[0] *= cor0; lacc[1] *= cor0;
        lacc[2] *= cor1; lacc[3] *= cor1;
        #pragma unroll
        for (int d = 0; d < 4; d++) {
            oc[d][0] *= cor0; oc[d][1] *= cor0;
            oc[d][2] *= cor1; oc[d][3] *= cor1;
        }

        // ---- O += P V ; l += P·1 (ones-MMA) ----
        #pragma unroll
        for (int kk = 0; kk < 4; kk++) {
            uint32_t vb0, vb1, vb2, vb3, wb0, wb1, wb2, wb3;
            ldsm_x4_t(vb0, vb1, vb2, vb3, smem_u32(&Vs[16*kk + vrow][vcol]));
            ldsm_x4_t(wb0, wb1, wb2, wb3, smem_u32(&Vs[16*kk + vrow][16 + vcol]));
            uint32_t a0 = pf[2*kk][0], a1 = pf[2*kk][1];
            uint32_t a2 = pf[2*kk+1][0], a3 = pf[2*kk+1][1];
            mma16816(oc[0], a0, a1, a2, a3, vb0, vb1);
            mma16816(oc[1], a0, a1, a2, a3, vb2, vb3);
            mma16816(oc[2], a0, a1, a2, a3, wb0, wb1);
            mma16816(oc[3], a0, a1, a2, a3, wb2, wb3);
            mma16816(lacc,  a0, a1, a2, a3, ONES, ONES);
        }
    }

    // ---- epilogue: normalize, write g_O [l][b][e] ----
    const float inv0 = 1.f / lacc[0], inv1 = 1.f / lacc[2];
    const int r = lane >> 2, c = (lane & 3) * 2;
    const int b = bh >> 3, h = bh & 7;
    const int qrow0 = q0 + 16*warp + r;
    const int qrow1 = qrow0 + 8;
    #pragma unroll
    for (int d = 0; d < 4; d++) {
        float2 v0 = make_float2(oc[d][0] * inv0, oc[d][1] * inv0);
        float2 v1 = make_float2(oc[d][2] * inv1, oc[d][3] * inv1);
        *(float2*)&g_O[((size_t)qrow0 * NB + b) * EMB + h * HD + 8*d + c] = v0;
        *(float2*)&g_O[((size_t)qrow1 * NB + b) * EMB + h * HD + 8*d + c] = v1;
    }
}

// ============================================================
extern "C" void kernel_launch(void* const* d_in, const int* in_sizes, int n_in,
                              void* d_out, int out_size)
{
    const float* query = (const float*)d_in[0];
    const float* key_  = (const float*)d_in[1];
    const float* value = (const float*)d_in[2];
    const float* Wq    = (const float*)d_in[3];
    const float* bq    = (const float*)d_in[4];
    const float* Wk    = (const float*)d_in[5];
    const float* bk    = (const float*)d_in[6];
    const float* Wv    = (const float*)d_in[7];
    const float* bv    = (const float*)d_in[8];
    const float* Wp    = (const float*)d_in[9];
    const float* bp    = (const float*)d_in[10];
    float* out = (float*)d_out;

    dim3 g1(MROWS/64, EMB/64, 3);
    split_gemm<<<g1, 128>>>(0, query, key_, value, Wq, bq, Wk, bk, Wv, bv, Wp, bp, out);

    dim3 g2(LSEQ/64, NB*NH);
    attn_kernel<<<g2, 128>>>();

    dim3 g3(MROWS/64, EMB/64, 1);
    split_gemm<<<g3, 128>>>(3, query, key_, value, Wq, bq, Wk, bk, Wv, bv, Wp, bp, out);
}